// round 14
// baseline (speedup 1.0000x reference)
#include <cuda_runtime.h>
#include <cuda_fp16.h>
#include <cstdint>

#define B_  2
#define S_  2048
#define DIM_ 2048
#define NH_ 16
#define HD_ 128
#define MROWS (B_*S_)          // 4096
#define KVSPLIT 8
#define NW_ (DIM_*DIM_)        // 4194304 = 2^22

// ---------------- scratch (device globals; no allocation) ----------------
__device__ __align__(16) float g_Mp[(size_t)KVSPLIT * B_ * NH_ * HD_ * HD_];

__device__ __align__(16) __half g_xf[(size_t)MROWS * DIM_];
__device__ __align__(16) __half g_w[4][(size_t)NW_];
__device__ __align__(16) __half g_af[(size_t)MROWS * DIM_];
__device__ __align__(16) __half g_qf[(size_t)MROWS * DIM_];
__device__ __align__(16) __half g_ktf[(size_t)B_ * NH_ * HD_ * S_];
__device__ __align__(16) __half g_vt [(size_t)B_ * NH_ * HD_ * S_];
__device__ __align__(16) __half g_mtf[(size_t)B_ * NH_ * HD_ * HD_];

// ======================= PTX helpers ==========================
__device__ __forceinline__ uint32_t smem_u32(const void* p) {
    uint32_t a;
    asm("{ .reg .u64 t; cvta.to.shared.u64 t, %1; cvt.u32.u64 %0, t; }"
        : "=r"(a) : "l"(p));
    return a;
}

__device__ __forceinline__ void ldsm_x4(uint32_t* r, uint32_t addr) {
    asm volatile("ldmatrix.sync.aligned.m8n8.x4.shared.b16 {%0,%1,%2,%3}, [%4];"
                 : "=r"(r[0]), "=r"(r[1]), "=r"(r[2]), "=r"(r[3]) : "r"(addr));
}

__device__ __forceinline__ void mma_f16(float* d, const uint32_t* a, const uint32_t* b) {
    asm volatile(
        "mma.sync.aligned.m16n8k16.row.col.f32.f16.f16.f32 "
        "{%0,%1,%2,%3}, {%4,%5,%6,%7}, {%8,%9}, {%0,%1,%2,%3};"
        : "+f"(d[0]), "+f"(d[1]), "+f"(d[2]), "+f"(d[3])
        : "r"(a[0]), "r"(a[1]), "r"(a[2]), "r"(a[3]), "r"(b[0]), "r"(b[1]));
}

#define CP_ASYNC16(dst, src) \
    asm volatile("cp.async.cg.shared.global [%0], [%1], 16;" :: "r"(dst), "l"(src))
#define CP_COMMIT() asm volatile("cp.async.commit_group;" ::: "memory")
#define CP_WAIT0()  asm volatile("cp.async.wait_group 0;" ::: "memory")
#define CP_WAIT1()  asm volatile("cp.async.wait_group 1;" ::: "memory")

#define SW128(bo) ((bo) ^ (((bo) >> 3) & 0x70))

#define ACC_INIT4(acc) \
    _Pragma("unroll") for (int i = 0; i < 4; i++) \
    _Pragma("unroll") for (int j = 0; j < 4; j++) \
    _Pragma("unroll") for (int q = 0; q < 4; q++) acc[i][j][q] = 0.f;

// ============ fp16 1-pass 128x128 mainloop, 256 thr (small GEMMs) ==========
#define STAGE1_BYTES 32768
#define GEMM1_SMEM   (3 * STAGE1_BYTES)

__device__ __forceinline__ void mm_tile1(
    const __half* Af, const __half* Bf,
    int lda, int ldb, int chunks, char* smem, float (&acc)[4][4][4])
{
    const uint32_t sbase = smem_u32(smem);
    const int tid  = threadIdx.x;
    const int lane = tid & 31;
    const int w    = tid >> 5;
    const int wm   = (w & 1) * 64;
    const int wn   = (w >> 1) * 32;

    auto stage_load = [&](int buf, int kbase) {
        const uint32_t sp0 = sbase + buf * STAGE1_BYTES;
#pragma unroll
        for (int m = 0; m < 2; m++) {
            const __half* gp = (m ? Bf : Af) + kbase;
            const int ld = m ? ldb : lda;
            const uint32_t sp = sp0 + m * 16384;
#pragma unroll
            for (int j = 0; j < 4; j++) {
                int id  = j * 256 + tid;
                int row = id >> 3;
                int ch  = id & 7;
                uint32_t bo = row * 128 + ch * 16;
                CP_ASYNC16(sp + SW128(bo), (const char*)(gp + (size_t)row * ld) + ch * 16);
            }
        }
    };

    stage_load(0, 0);
    CP_COMMIT();
    if (chunks > 1) { stage_load(1, 64); CP_COMMIT(); }

    const int a_row  = lane & 15;
    const int a_koff = (lane >> 4) * 16;
    const int b_row  = (lane & 7) + ((lane >> 4) << 3);
    const int b_koff = ((lane >> 3) & 1) * 16;

    int buf = 0;
    for (int c = 0; c < chunks; c++) {
        if (c + 1 < chunks) CP_WAIT1(); else CP_WAIT0();
        __syncthreads();
        if (c + 2 < chunks) {
            int nb = buf + 2; if (nb >= 3) nb -= 3;
            stage_load(nb, (c + 2) * 64);
            CP_COMMIT();
        }

        const uint32_t sA = sbase + buf * STAGE1_BYTES;
        const uint32_t sB = sA + 16384;

#pragma unroll
        for (int ks = 0; ks < 4; ks++) {
            const int kb2 = ks * 32;
            uint32_t af[4][4], bf[2][4];
#pragma unroll
            for (int mt = 0; mt < 4; mt++) {
                uint32_t bo = (wm + mt * 16 + a_row) * 128 + kb2 + a_koff;
                ldsm_x4(af[mt], sA + SW128(bo));
            }
#pragma unroll
            for (int bt = 0; bt < 2; bt++) {
                uint32_t bo = (wn + bt * 16 + b_row) * 128 + kb2 + b_koff;
                ldsm_x4(bf[bt], sB + SW128(bo));
            }
#pragma unroll
            for (int mt = 0; mt < 4; mt++) {
#pragma unroll
                for (int nt = 0; nt < 4; nt++) {
                    const uint32_t* bp = &bf[nt >> 1][(nt & 1) * 2];
                    mma_f16(acc[mt][nt], af[mt], bp);
                }
            }
        }
        if (++buf == 3) buf = 0;
    }
}

// ============ fp16 1-pass 256x128 mainloop, 512 thr (big GEMMs) ============
// 16 warps as 4(M)x4(N); warp tile 64x32 (per-thread state == 256-thr loop).
// Stage: A 32KB (256x128B) + B 16KB (128x128B) = 48KB; 3 stages, 1 CTA/SM.
#define STAGE5_BYTES 49152
#define GEMM5_SMEM   (3 * STAGE5_BYTES)

__device__ __forceinline__ void mm_tile5(
    const __half* Af, const __half* Bf,
    int lda, int ldb, int chunks, char* smem, float (&acc)[4][4][4])
{
    const uint32_t sbase = smem_u32(smem);
    const int tid  = threadIdx.x;
    const int lane = tid & 31;
    const int w    = tid >> 5;
    const int wm   = (w & 3) * 64;     // 0..192
    const int wn   = (w >> 2) * 32;    // 0..96

    auto stage_load = [&](int buf, int kbase) {
        const uint32_t sp0 = sbase + buf * STAGE5_BYTES;
        // A: 256 rows x 128B = 2048 uint4 -> 4 iters x 512 thr
        {
            const __half* gp = Af + kbase;
#pragma unroll
            for (int j = 0; j < 4; j++) {
                int id  = j * 512 + tid;
                int row = id >> 3;
                int ch  = id & 7;
                uint32_t bo = row * 128 + ch * 16;
                CP_ASYNC16(sp0 + SW128(bo), (const char*)(gp + (size_t)row * lda) + ch * 16);
            }
        }
        // B: 128 rows x 128B = 1024 uint4 -> 2 iters x 512 thr
        {
            const __half* gp = Bf + kbase;
            const uint32_t sp = sp0 + 32768;
#pragma unroll
            for (int j = 0; j < 2; j++) {
                int id  = j * 512 + tid;
                int row = id >> 3;
                int ch  = id & 7;
                uint32_t bo = row * 128 + ch * 16;
                CP_ASYNC16(sp + SW128(bo), (const char*)(gp + (size_t)row * ldb) + ch * 16);
            }
        }
    };

    stage_load(0, 0);
    CP_COMMIT();
    if (chunks > 1) { stage_load(1, 64); CP_COMMIT(); }

    const int a_row  = lane & 15;
    const int a_koff = (lane >> 4) * 16;
    const int b_row  = (lane & 7) + ((lane >> 4) << 3);
    const int b_koff = ((lane >> 3) & 1) * 16;

    int buf = 0;
    for (int c = 0; c < chunks; c++) {
        if (c + 1 < chunks) CP_WAIT1(); else CP_WAIT0();
        __syncthreads();
        if (c + 2 < chunks) {
            int nb = buf + 2; if (nb >= 3) nb -= 3;
            stage_load(nb, (c + 2) * 64);
            CP_COMMIT();
        }

        const uint32_t sA = sbase + buf * STAGE5_BYTES;
        const uint32_t sB = sA + 32768;

#pragma unroll
        for (int ks = 0; ks < 4; ks++) {
            const int kb2 = ks * 32;
            uint32_t af[4][4], bf[2][4];
#pragma unroll
            for (int mt = 0; mt < 4; mt++) {
                uint32_t bo = (wm + mt * 16 + a_row) * 128 + kb2 + a_koff;
                ldsm_x4(af[mt], sA + SW128(bo));
            }
#pragma unroll
            for (int bt = 0; bt < 2; bt++) {
                uint32_t bo = (wn + bt * 16 + b_row) * 128 + kb2 + b_koff;
                ldsm_x4(bf[bt], sB + SW128(bo));
            }
#pragma unroll
            for (int mt = 0; mt < 4; mt++) {
#pragma unroll
                for (int nt = 0; nt < 4; nt++) {
                    const uint32_t* bp = &bf[nt >> 1][(nt & 1) * 2];
                    mma_f16(acc[mt][nt], af[mt], bp);
                }
            }
        }
        if (++buf == 3) buf = 0;
    }
}

// ============ fused QKV GEMM + rope/round/transpose epilogue ===============
// grid (48, 16), 512 thr. CTA tile 256(s) x 128(one head).
//   wsel 0 (Q): bias+rope -> round -> qf row-major
//   wsel 1 (K): bias+rope -> round -> transpose -> ktf [bh][d][s]
//   wsel 2 (V): bias      -> round -> transpose -> vt  [bh][d][s]
#define TPAD 264   // 256 s + 8 pad

__global__ void __launch_bounds__(512, 1)
gemm_qkv(const __half* __restrict__ xf, const __half* __restrict__ wf,
         const float* __restrict__ bq, const float* __restrict__ bk,
         const float* __restrict__ bv,
         const float* __restrict__ fc, const float* __restrict__ fs,
         __half* __restrict__ qf, __half* __restrict__ ktf,
         __half* __restrict__ vt)
{
    extern __shared__ char smem[];
    const int bx = blockIdx.x, by = blockIdx.y;
    const int wsel = bx >> 4;
    const int col0 = (bx & 15) * 128;
    const int row0 = by * 256;

    float acc[4][4][4];
    ACC_INIT4(acc)
    mm_tile5(xf + (size_t)row0 * DIM_, wf + (size_t)bx * 128 * DIM_,
             DIM_, DIM_, DIM_ / 64, smem, acc);

    // single-barrier mainloop has no trailing sync; transpose buffer below
    // overlaps stage memory.
    __syncthreads();

    const int tid  = threadIdx.x;
    const int lane = tid & 31, w = tid >> 5;
    const int wm = (w & 3) * 64, wn = (w >> 2) * 32;
    const int l4 = lane >> 2, l2 = (lane & 3) * 2;

    const int s0 = (by & 7) * 256;    // s offset within batch
    const int b  = by >> 3;
    const int h  = bx & 15;

    if (wsel == 0) {
        // ---- Q: bias + rope + round, row-major ----
#pragma unroll
        for (int mt = 0; mt < 4; mt++) {
#pragma unroll
            for (int nt = 0; nt < 4; nt++) {
                const int cl = wn + nt * 8 + l2;        // even, within-head dim
                const int i  = cl >> 1;
                const float b0 = __ldg(bq + col0 + cl);
                const float b1 = __ldg(bq + col0 + cl + 1);
#pragma unroll
                for (int rr = 0; rr < 2; rr++) {
                    const int sl = wm + mt * 16 + l4 + rr * 8;
                    const int sg = s0 + sl;
                    const float c  = __ldg(fc + sg * 64 + i);
                    const float sn = __ldg(fs + sg * 64 + i);
                    const float v0 = acc[mt][nt][rr * 2 + 0] + b0;
                    const float v1 = acc[mt][nt][rr * 2 + 1] + b1;
                    const float o0 = v0 * c - v1 * sn;
                    const float o1 = v0 * sn + v1 * c;
                    const size_t off = (size_t)(row0 + sl) * DIM_ + col0 + cl;
                    *(__half2*)(qf + off) = __floats2half2_rn(o0, o1);
                }
            }
        }
    } else {
        // ---- K / V: round into transposed smem buffer [128 d][256 s] ----
        __half* sh = (__half*)smem;
        const float* bias = (wsel == 1) ? bk : bv;
#pragma unroll
        for (int mt = 0; mt < 4; mt++) {
#pragma unroll
            for (int nt = 0; nt < 4; nt++) {
                const int cl = wn + nt * 8 + l2;
                const float b0 = __ldg(bias + col0 + cl);
                const float b1 = __ldg(bias + col0 + cl + 1);
#pragma unroll
                for (int rr = 0; rr < 2; rr++) {
                    const int sl = wm + mt * 16 + l4 + rr * 8;
                    float v0 = acc[mt][nt][rr * 2 + 0] + b0;
                    float v1 = acc[mt][nt][rr * 2 + 1] + b1;
                    if (wsel == 1) {
                        const int i  = cl >> 1;
                        const int sg = s0 + sl;
                        const float c  = __ldg(fc + sg * 64 + i);
                        const float sn = __ldg(fs + sg * 64 + i);
                        const float o0 = v0 * c - v1 * sn;
                        const float o1 = v0 * sn + v1 * c;
                        v0 = o0; v1 = o1;
                    }
                    sh[cl * TPAD + sl]       = __float2half(v0);
                    sh[(cl + 1) * TPAD + sl] = __float2half(v1);
                }
            }
        }
        __syncthreads();
        const size_t tb = ((size_t)(b * NH_ + h)) * HD_ * S_ + s0;
        const int d  = tid >> 2;
        const int sc = (tid & 3) * 64;
        __half* dst = (wsel == 1) ? ktf : vt;
#pragma unroll
        for (int j = 0; j < 8; j++) {
            const size_t go = tb + (size_t)d * S_ + sc + j * 8;
            *(uint4*)(dst + go) = *(const uint4*)&sh[d * TPAD + sc + j * 8];
        }
    }
}

// ============ WO GEMM: grid (16, 16), 512 thr, CTA 256x128 =================
__global__ void __launch_bounds__(512, 1)
gemm_wo(const __half* __restrict__ Af, const __half* __restrict__ Bf,
        const float* __restrict__ bias, float* __restrict__ C)
{
    extern __shared__ char smem[];
    const int row0 = blockIdx.y * 256;
    const int col0 = blockIdx.x * 128;

    float acc[4][4][4];
    ACC_INIT4(acc)
    mm_tile5(Af + (size_t)row0 * DIM_, Bf + (size_t)col0 * DIM_,
             DIM_, DIM_, DIM_ / 64, smem, acc);

    const int lane = threadIdx.x & 31, w = threadIdx.x >> 5;
    const int wm = (w & 3) * 64, wn = (w >> 2) * 32;
    const int l4 = lane >> 2, l2 = (lane & 3) * 2;
#pragma unroll
    for (int mt = 0; mt < 4; mt++) {
#pragma unroll
        for (int nt = 0; nt < 4; nt++) {
            int grow = row0 + wm + mt * 16 + l4;
            int gcol = col0 + wn + nt * 8 + l2;
            float b0 = __ldg(bias + gcol);
            float b1 = __ldg(bias + gcol + 1);
            float* cp0 = C + (size_t)grow * DIM_ + gcol;
            float* cp1 = cp0 + 8 * (size_t)DIM_;
            *(float2*)cp0 = make_float2(acc[mt][nt][0] + b0, acc[mt][nt][1] + b1);
            *(float2*)cp1 = make_float2(acc[mt][nt][2] + b0, acc[mt][nt][3] + b1);
        }
    }
}

// ============ KtV GEMM (fp16 1-pass): grid (KVSPLIT, 32) ===================
__global__ void __launch_bounds__(256, 2)
kv_hmma(const __half* __restrict__ ktf, const __half* __restrict__ vt,
        float* __restrict__ Mp)
{
    extern __shared__ char smem[];
    const int ksp = blockIdx.x;
    const int bh  = blockIdx.y;
    const size_t base = (size_t)bh * HD_ * S_ + ksp * (S_ / KVSPLIT);

    float acc[4][4][4];
    ACC_INIT4(acc)
    mm_tile1(ktf + base, vt + base, S_, S_, (S_ / KVSPLIT) / 64, smem, acc);

    float* C = Mp + ((size_t)ksp * 32 + bh) * (HD_ * HD_);
    const int lane = threadIdx.x & 31, w = threadIdx.x >> 5;
    const int wm = (w & 1) * 64, wn = (w >> 1) * 32;
    const int l4 = lane >> 2, l2 = (lane & 3) * 2;
#pragma unroll
    for (int mt = 0; mt < 4; mt++) {
#pragma unroll
        for (int nt = 0; nt < 4; nt++) {
            int grow = wm + mt * 16 + l4;
            int gcol = wn + nt * 8 + l2;
            float* cp0 = C + (size_t)grow * HD_ + gcol;
            float* cp1 = cp0 + 8 * HD_;
            *(float2*)cp0 = make_float2(acc[mt][nt][0], acc[mt][nt][1]);
            *(float2*)cp1 = make_float2(acc[mt][nt][2], acc[mt][nt][3]);
        }
    }
}

// ============ attn GEMM (fp16 1-pass): grid (16,32) ========================
__global__ void __launch_bounds__(256, 2)
attn_hmma(const __half* __restrict__ qf, const __half* __restrict__ mtf,
          __half* __restrict__ af)
{
    extern __shared__ char smem[];
    const int st = blockIdx.x;
    const int bh = blockIdx.y;
    const int b = bh >> 4, h = bh & 15;
    const size_t abase = ((size_t)(b * S_ + st * 128)) * DIM_ + h * HD_;
    const size_t mbase = (size_t)bh * HD_ * HD_;

    float acc[4][4][4];
    ACC_INIT4(acc)
    mm_tile1(qf + abase, mtf + mbase, DIM_, HD_, HD_ / 64, smem, acc);

    const int lane = threadIdx.x & 31, w = threadIdx.x >> 5;
    const int wm = (w & 1) * 64, wn = (w >> 1) * 32;
    const int l4 = lane >> 2, l2 = (lane & 3) * 2;
#pragma unroll
    for (int mt = 0; mt < 4; mt++) {
#pragma unroll
        for (int nt = 0; nt < 4; nt++) {
            size_t off0 = abase + (size_t)(wm + mt * 16 + l4) * DIM_ + wn + nt * 8 + l2;
            size_t off1 = off0 + 8 * (size_t)DIM_;
            *(__half2*)(af + off0) = __floats2half2_rn(acc[mt][nt][0], acc[mt][nt][1]);
            *(__half2*)(af + off1) = __floats2half2_rn(acc[mt][nt][2], acc[mt][nt][3]);
        }
    }
}

// ============ reduce Mp over splits, scale, transpose, round ===============
__global__ void reduce_mt(const float* __restrict__ Mp, __half* __restrict__ mt)
{
    int o = blockIdx.x * 256 + threadIdx.x;
    int bh = o >> 13;
    int r  = o & 8191;
    int d  = r >> 6;
    int d2p = (r & 63) * 2;
    const float* src = Mp + (size_t)bh * (HD_ * HD_) + (size_t)d2p * HD_ + d;
    float s0 = 0.f, s1 = 0.f;
    const size_t stride = (size_t)32 * HD_ * HD_;
#pragma unroll
    for (int p = 0; p < KVSPLIT; p++) {
        s0 += src[p * stride];
        s1 += src[p * stride + HD_];
    }
    s0 *= 0.08838834764831845f;
    s1 *= 0.08838834764831845f;
    size_t off = (size_t)bh * (HD_ * HD_) + (size_t)d * HD_ + d2p;
    *(__half2*)(mt + off) = __floats2half2_rn(s0, s1);
}

// ---------------- fp32 -> fp16 round ---------------------------------------
__global__ void round_fp16(const float* __restrict__ x, __half* __restrict__ o, int n)
{
    int i = (blockIdx.x * 256 + threadIdx.x) * 4;
    if (i >= n) return;
    float4 v = *(const float4*)(x + i);
    ((__half2*)(o + i))[0] = __floats2half2_rn(v.x, v.y);
    ((__half2*)(o + i))[1] = __floats2half2_rn(v.z, v.w);
}

// ---------------- fused 4-weight fp32 -> fp16 round ------------------------
__global__ void round_w4(const float* __restrict__ w0, const float* __restrict__ w1,
                         const float* __restrict__ w2, const float* __restrict__ w3,
                         __half* __restrict__ o)
{
    int t = (blockIdx.x * 256 + threadIdx.x) * 4;
    int seg = t >> 22;                 // NW_ = 2^22
    int off = t & (NW_ - 1);
    const float* src = (seg == 0) ? w0 : (seg == 1) ? w1 : (seg == 2) ? w2 : w3;
    float4 v = *(const float4*)(src + off);
    ((__half2*)(o + t))[0] = __floats2half2_rn(v.x, v.y);
    ((__half2*)(o + t))[1] = __floats2half2_rn(v.z, v.w);
}

// ---------------------------------------------------------------------------
extern "C" void kernel_launch(void* const* d_in, const int* in_sizes, int n_in,
                              void* d_out, int out_size)
{
    const float* x  = (const float*)d_in[0];
    const float* fc = (const float*)d_in[1];
    const float* fs = (const float*)d_in[2];
    const float* wq = (const float*)d_in[3];
    const float* bq = (const float*)d_in[4];
    const float* wk = (const float*)d_in[5];
    const float* bk = (const float*)d_in[6];
    const float* wv = (const float*)d_in[7];
    const float* bv = (const float*)d_in[8];
    const float* wo = (const float*)d_in[9];
    const float* bo = (const float*)d_in[10];
    float* out = (float*)d_out;

    float *pMp;
    __half *pxf, *pw, *paf, *pqf, *pktf, *pvt, *pmtf;
    cudaGetSymbolAddress((void**)&pMp, g_Mp);
    cudaGetSymbolAddress((void**)&pxf, g_xf);
    cudaGetSymbolAddress((void**)&pw,  g_w);
    cudaGetSymbolAddress((void**)&paf, g_af);
    cudaGetSymbolAddress((void**)&pqf, g_qf);
    cudaGetSymbolAddress((void**)&pktf, g_ktf);
    cudaGetSymbolAddress((void**)&pvt, g_vt);
    cudaGetSymbolAddress((void**)&pmtf, g_mtf);

    cudaFuncSetAttribute(gemm_qkv,  cudaFuncAttributeMaxDynamicSharedMemorySize, GEMM5_SMEM);
    cudaFuncSetAttribute(gemm_wo,   cudaFuncAttributeMaxDynamicSharedMemorySize, GEMM5_SMEM);
    cudaFuncSetAttribute(kv_hmma,   cudaFuncAttributeMaxDynamicSharedMemorySize, GEMM1_SMEM);
    cudaFuncSetAttribute(attn_hmma, cudaFuncAttributeMaxDynamicSharedMemorySize, GEMM1_SMEM);

    dim3 blk(256);
    dim3 blk5(512);
    const int NX = MROWS * DIM_;
    const size_t WSTRIDE = (size_t)NW_;

    round_fp16<<<NX / 1024, blk>>>(x, pxf, NX);
    round_w4<<<4 * NW_ / 1024, blk>>>(wq, wk, wv, wo, pw);

    gemm_qkv<<<dim3(48, 16), blk5, GEMM5_SMEM>>>(pxf, pw, bq, bk, bv, fc, fs,
                                                 pqf, pktf, pvt);

    kv_hmma<<<dim3(KVSPLIT, 32), blk, GEMM1_SMEM>>>(pktf, pvt, pMp);

    reduce_mt<<<(32 * HD_ * HD_ / 2) / 256, blk>>>(pMp, pmtf);

    attn_hmma<<<dim3(16, 32), blk, GEMM1_SMEM>>>(pqf, pmtf, paf);

    gemm_wo<<<dim3(16, 16), blk5, GEMM5_SMEM>>>(paf, pw + 3 * WSTRIDE, bo, out);
}

// round 15
// speedup vs baseline: 1.0918x; 1.0918x over previous
#include <cuda_runtime.h>
#include <cuda_fp16.h>
#include <cstdint>

#define B_  2
#define S_  2048
#define DIM_ 2048
#define NH_ 16
#define HD_ 128
#define MROWS (B_*S_)          // 4096
#define KVSPLIT 16
#define NW_ (DIM_*DIM_)        // 4194304 = 2^22
#define NX_ (MROWS*DIM_)       // 8388608 = 2*2^22

// ---------------- scratch (device globals; no allocation) ----------------
__device__ __align__(16) float g_Mp[(size_t)KVSPLIT * B_ * NH_ * HD_ * HD_];

__device__ __align__(16) __half g_xf[(size_t)NX_];
__device__ __align__(16) __half g_w[4][(size_t)NW_];
__device__ __align__(16) __half g_af[(size_t)NX_];
__device__ __align__(16) __half g_qf[(size_t)NX_];
__device__ __align__(16) __half g_ktf[(size_t)B_ * NH_ * HD_ * S_];
__device__ __align__(16) __half g_vt [(size_t)B_ * NH_ * HD_ * S_];
__device__ __align__(16) __half g_mtf[(size_t)B_ * NH_ * HD_ * HD_];

// ======================= PTX helpers ==========================
__device__ __forceinline__ uint32_t smem_u32(const void* p) {
    uint32_t a;
    asm("{ .reg .u64 t; cvta.to.shared.u64 t, %1; cvt.u32.u64 %0, t; }"
        : "=r"(a) : "l"(p));
    return a;
}

__device__ __forceinline__ void ldsm_x4(uint32_t* r, uint32_t addr) {
    asm volatile("ldmatrix.sync.aligned.m8n8.x4.shared.b16 {%0,%1,%2,%3}, [%4];"
                 : "=r"(r[0]), "=r"(r[1]), "=r"(r[2]), "=r"(r[3]) : "r"(addr));
}

__device__ __forceinline__ void mma_f16(float* d, const uint32_t* a, const uint32_t* b) {
    asm volatile(
        "mma.sync.aligned.m16n8k16.row.col.f32.f16.f16.f32 "
        "{%0,%1,%2,%3}, {%4,%5,%6,%7}, {%8,%9}, {%0,%1,%2,%3};"
        : "+f"(d[0]), "+f"(d[1]), "+f"(d[2]), "+f"(d[3])
        : "r"(a[0]), "r"(a[1]), "r"(a[2]), "r"(a[3]), "r"(b[0]), "r"(b[1]));
}

#define CP_ASYNC16(dst, src) \
    asm volatile("cp.async.cg.shared.global [%0], [%1], 16;" :: "r"(dst), "l"(src))
#define CP_COMMIT() asm volatile("cp.async.commit_group;" ::: "memory")
#define CP_WAIT0()  asm volatile("cp.async.wait_group 0;" ::: "memory")
#define CP_WAIT1()  asm volatile("cp.async.wait_group 1;" ::: "memory")

#define SW128(bo) ((bo) ^ (((bo) >> 3) & 0x70))

#define ACC_INIT4(acc) \
    _Pragma("unroll") for (int i = 0; i < 4; i++) \
    _Pragma("unroll") for (int j = 0; j < 4; j++) \
    _Pragma("unroll") for (int q = 0; q < 4; q++) acc[i][j][q] = 0.f;

// ============ fp16 1-pass 128x128 mainloop, 3-stage, single barrier ========
#define STAGE1_BYTES 32768
#define GEMM1_SMEM   (3 * STAGE1_BYTES)

__device__ __forceinline__ void mm_tile1(
    const __half* Af, const __half* Bf,
    int lda, int ldb, int chunks, char* smem, float (&acc)[4][4][4])
{
    const uint32_t sbase = smem_u32(smem);
    const int tid  = threadIdx.x;
    const int lane = tid & 31;
    const int w    = tid >> 5;
    const int wm   = (w & 1) * 64;
    const int wn   = (w >> 1) * 32;

    auto stage_load = [&](int buf, int kbase) {
        const uint32_t sp0 = sbase + buf * STAGE1_BYTES;
#pragma unroll
        for (int m = 0; m < 2; m++) {
            const __half* gp = (m ? Bf : Af) + kbase;
            const int ld = m ? ldb : lda;
            const uint32_t sp = sp0 + m * 16384;
#pragma unroll
            for (int j = 0; j < 4; j++) {
                int id  = j * 256 + tid;
                int row = id >> 3;
                int ch  = id & 7;
                uint32_t bo = row * 128 + ch * 16;
                CP_ASYNC16(sp + SW128(bo), (const char*)(gp + (size_t)row * ld) + ch * 16);
            }
        }
    };

    stage_load(0, 0);
    CP_COMMIT();
    if (chunks > 1) { stage_load(1, 64); CP_COMMIT(); }

    const int a_row  = lane & 15;
    const int a_koff = (lane >> 4) * 16;
    const int b_row  = (lane & 7) + ((lane >> 4) << 3);
    const int b_koff = ((lane >> 3) & 1) * 16;

    int buf = 0;
    for (int c = 0; c < chunks; c++) {
        if (c + 1 < chunks) CP_WAIT1(); else CP_WAIT0();
        __syncthreads();
        if (c + 2 < chunks) {
            int nb = buf + 2; if (nb >= 3) nb -= 3;
            stage_load(nb, (c + 2) * 64);
            CP_COMMIT();
        }

        const uint32_t sA = sbase + buf * STAGE1_BYTES;
        const uint32_t sB = sA + 16384;

#pragma unroll
        for (int ks = 0; ks < 4; ks++) {
            const int kb2 = ks * 32;
            uint32_t af[4][4], bf[2][4];
#pragma unroll
            for (int mt = 0; mt < 4; mt++) {
                uint32_t bo = (wm + mt * 16 + a_row) * 128 + kb2 + a_koff;
                ldsm_x4(af[mt], sA + SW128(bo));
            }
#pragma unroll
            for (int bt = 0; bt < 2; bt++) {
                uint32_t bo = (wn + bt * 16 + b_row) * 128 + kb2 + b_koff;
                ldsm_x4(bf[bt], sB + SW128(bo));
            }
#pragma unroll
            for (int mt = 0; mt < 4; mt++) {
#pragma unroll
                for (int nt = 0; nt < 4; nt++) {
                    const uint32_t* bp = &bf[nt >> 1][(nt & 1) * 2];
                    mma_f16(acc[mt][nt], af[mt], bp);
                }
            }
        }
        if (++buf == 3) buf = 0;
    }
}

// ============ fused QKV GEMM + rope/round/transpose epilogue ===============
// grid (48, 32). Column tile == one head (HD==128).
__global__ void __launch_bounds__(256, 2)
gemm_qkv(const __half* __restrict__ xf, const __half* __restrict__ wf,
         const float* __restrict__ bq, const float* __restrict__ bk,
         const float* __restrict__ bv,
         const float* __restrict__ fc, const float* __restrict__ fs,
         __half* __restrict__ qf, __half* __restrict__ ktf,
         __half* __restrict__ vt)
{
    extern __shared__ char smem[];
    const int bx = blockIdx.x, by = blockIdx.y;
    const int wsel = bx >> 4;
    const int col0 = (bx & 15) * 128;
    const int row0 = by * 128;

    float acc[4][4][4];
    ACC_INIT4(acc)
    mm_tile1(xf + (size_t)row0 * DIM_, wf + (size_t)bx * 128 * DIM_,
             DIM_, DIM_, DIM_ / 64, smem, acc);

    // single-barrier mainloop has no trailing sync; the transpose buffer below
    // overlaps stage memory, so order all lagging consumers before reuse.
    __syncthreads();

    const int tid  = threadIdx.x;
    const int lane = tid & 31, w = tid >> 5;
    const int wm = (w & 1) * 64, wn = (w >> 1) * 32;
    const int l4 = lane >> 2, l2 = (lane & 3) * 2;

    const int s0 = (by & 15) * 128;   // s offset within batch
    const int b  = by >> 4;
    const int h  = bx & 15;

    if (wsel == 0) {
        // ---- Q: bias + rope + round, row-major ----
#pragma unroll
        for (int mt = 0; mt < 4; mt++) {
#pragma unroll
            for (int nt = 0; nt < 4; nt++) {
                const int cl = wn + nt * 8 + l2;        // even, within-head dim
                const int i  = cl >> 1;
                const float b0 = __ldg(bq + col0 + cl);
                const float b1 = __ldg(bq + col0 + cl + 1);
#pragma unroll
                for (int rr = 0; rr < 2; rr++) {
                    const int sl = wm + mt * 16 + l4 + rr * 8;
                    const int sg = s0 + sl;
                    const float c  = __ldg(fc + sg * 64 + i);
                    const float sn = __ldg(fs + sg * 64 + i);
                    const float v0 = acc[mt][nt][rr * 2 + 0] + b0;
                    const float v1 = acc[mt][nt][rr * 2 + 1] + b1;
                    const float o0 = v0 * c - v1 * sn;
                    const float o1 = v0 * sn + v1 * c;
                    const size_t off = (size_t)(row0 + sl) * DIM_ + col0 + cl;
                    *(__half2*)(qf + off) = __floats2half2_rn(o0, o1);
                }
            }
        }
    } else {
        // ---- K / V: round into transposed smem buffer [128 d][136] ----
        __half* sh = (__half*)smem;
        const float* bias = (wsel == 1) ? bk : bv;
#pragma unroll
        for (int mt = 0; mt < 4; mt++) {
#pragma unroll
            for (int nt = 0; nt < 4; nt++) {
                const int cl = wn + nt * 8 + l2;
                const float b0 = __ldg(bias + col0 + cl);
                const float b1 = __ldg(bias + col0 + cl + 1);
#pragma unroll
                for (int rr = 0; rr < 2; rr++) {
                    const int sl = wm + mt * 16 + l4 + rr * 8;
                    float v0 = acc[mt][nt][rr * 2 + 0] + b0;
                    float v1 = acc[mt][nt][rr * 2 + 1] + b1;
                    if (wsel == 1) {
                        const int i  = cl >> 1;
                        const int sg = s0 + sl;
                        const float c  = __ldg(fc + sg * 64 + i);
                        const float sn = __ldg(fs + sg * 64 + i);
                        const float o0 = v0 * c - v1 * sn;
                        const float o1 = v0 * sn + v1 * c;
                        v0 = o0; v1 = o1;
                    }
                    sh[cl * 136 + sl]       = __float2half(v0);
                    sh[(cl + 1) * 136 + sl] = __float2half(v1);
                }
            }
        }
        __syncthreads();
        // coalesced store: warp w writes rows 16w..16w+15; per STG two rows,
        // 16 lanes x 16B contiguous per row (2 x 256B segments).
        const size_t tb = ((size_t)(b * NH_ + h)) * HD_ * S_ + s0;
        const int lrow = lane >> 4;           // 0/1
        const int loff = (lane & 15) * 8;     // halves
        __half* dst = (wsel == 1) ? ktf : vt;
#pragma unroll
        for (int j = 0; j < 8; j++) {
            const int d = w * 16 + j * 2 + lrow;
            const size_t go = tb + (size_t)d * S_ + loff;
            *(uint4*)(dst + go) = *(const uint4*)&sh[d * 136 + loff];
        }
    }
}

// ============ WO GEMM: grid (16, 32) =======================================
__global__ void __launch_bounds__(256, 2)
gemm_wo(const __half* __restrict__ Af, const __half* __restrict__ Bf,
        const float* __restrict__ bias, float* __restrict__ C)
{
    extern __shared__ char smem[];
    const int row0 = blockIdx.y * 128;
    const int col0 = blockIdx.x * 128;

    float acc[4][4][4];
    ACC_INIT4(acc)
    mm_tile1(Af + (size_t)row0 * DIM_, Bf + (size_t)col0 * DIM_,
             DIM_, DIM_, DIM_ / 64, smem, acc);

    const int lane = threadIdx.x & 31, w = threadIdx.x >> 5;
    const int wm = (w & 1) * 64, wn = (w >> 1) * 32;
    const int l4 = lane >> 2, l2 = (lane & 3) * 2;
#pragma unroll
    for (int mt = 0; mt < 4; mt++) {
#pragma unroll
        for (int nt = 0; nt < 4; nt++) {
            int grow = row0 + wm + mt * 16 + l4;
            int gcol = col0 + wn + nt * 8 + l2;
            float b0 = __ldg(bias + gcol);
            float b1 = __ldg(bias + gcol + 1);
            float* cp0 = C + (size_t)grow * DIM_ + gcol;
            float* cp1 = cp0 + 8 * (size_t)DIM_;
            *(float2*)cp0 = make_float2(acc[mt][nt][0] + b0, acc[mt][nt][1] + b1);
            *(float2*)cp1 = make_float2(acc[mt][nt][2] + b0, acc[mt][nt][3] + b1);
        }
    }
}

// ============ KtV GEMM (fp16 1-pass): grid (KVSPLIT, 32) ===================
__global__ void __launch_bounds__(256, 2)
kv_hmma(const __half* __restrict__ ktf, const __half* __restrict__ vt,
        float* __restrict__ Mp)
{
    extern __shared__ char smem[];
    const int ksp = blockIdx.x;
    const int bh  = blockIdx.y;
    const size_t base = (size_t)bh * HD_ * S_ + ksp * (S_ / KVSPLIT);

    float acc[4][4][4];
    ACC_INIT4(acc)
    mm_tile1(ktf + base, vt + base, S_, S_, (S_ / KVSPLIT) / 64, smem, acc);

    float* C = Mp + ((size_t)ksp * 32 + bh) * (HD_ * HD_);
    const int lane = threadIdx.x & 31, w = threadIdx.x >> 5;
    const int wm = (w & 1) * 64, wn = (w >> 1) * 32;
    const int l4 = lane >> 2, l2 = (lane & 3) * 2;
#pragma unroll
    for (int mt = 0; mt < 4; mt++) {
#pragma unroll
        for (int nt = 0; nt < 4; nt++) {
            int grow = wm + mt * 16 + l4;
            int gcol = wn + nt * 8 + l2;
            float* cp0 = C + (size_t)grow * HD_ + gcol;
            float* cp1 = cp0 + 8 * HD_;
            *(float2*)cp0 = make_float2(acc[mt][nt][0], acc[mt][nt][1]);
            *(float2*)cp1 = make_float2(acc[mt][nt][2], acc[mt][nt][3]);
        }
    }
}

// ============ attn GEMM (fp16 1-pass): grid (16,32) ========================
__global__ void __launch_bounds__(256, 2)
attn_hmma(const __half* __restrict__ qf, const __half* __restrict__ mtf,
          __half* __restrict__ af)
{
    extern __shared__ char smem[];
    const int st = blockIdx.x;
    const int bh = blockIdx.y;
    const int b = bh >> 4, h = bh & 15;
    const size_t abase = ((size_t)(b * S_ + st * 128)) * DIM_ + h * HD_;
    const size_t mbase = (size_t)bh * HD_ * HD_;

    float acc[4][4][4];
    ACC_INIT4(acc)
    mm_tile1(qf + abase, mtf + mbase, DIM_, HD_, HD_ / 64, smem, acc);

    const int lane = threadIdx.x & 31, w = threadIdx.x >> 5;
    const int wm = (w & 1) * 64, wn = (w >> 1) * 32;
    const int l4 = lane >> 2, l2 = (lane & 3) * 2;
#pragma unroll
    for (int mt = 0; mt < 4; mt++) {
#pragma unroll
        for (int nt = 0; nt < 4; nt++) {
            size_t off0 = abase + (size_t)(wm + mt * 16 + l4) * DIM_ + wn + nt * 8 + l2;
            size_t off1 = off0 + 8 * (size_t)DIM_;
            *(__half2*)(af + off0) = __floats2half2_rn(acc[mt][nt][0], acc[mt][nt][1]);
            *(__half2*)(af + off1) = __floats2half2_rn(acc[mt][nt][2], acc[mt][nt][3]);
        }
    }
}

// ============ reduce Mp over splits, scale, transpose, round ===============
__global__ void reduce_mt(const float* __restrict__ Mp, __half* __restrict__ mt)
{
    int o = blockIdx.x * 256 + threadIdx.x;
    int bh = o >> 13;
    int r  = o & 8191;
    int d  = r >> 6;
    int d2p = (r & 63) * 2;
    const float* src = Mp + (size_t)bh * (HD_ * HD_) + (size_t)d2p * HD_ + d;
    float s0 = 0.f, s1 = 0.f;
    const size_t stride = (size_t)32 * HD_ * HD_;
#pragma unroll
    for (int p = 0; p < KVSPLIT; p++) {
        s0 += src[p * stride];
        s1 += src[p * stride + HD_];
    }
    s0 *= 0.08838834764831845f;
    s1 *= 0.08838834764831845f;
    size_t off = (size_t)bh * (HD_ * HD_) + (size_t)d * HD_ + d2p;
    *(__half2*)(mt + off) = __floats2half2_rn(s0, s1);
}

// ---------------- fused x + 4-weight fp32 -> fp16 round --------------------
// segments of 2^22 elems: [0,1]=x, [2..5]=wq,wk,wv,wo
__global__ void round_all(const float* __restrict__ x,
                          const float* __restrict__ w0, const float* __restrict__ w1,
                          const float* __restrict__ w2, const float* __restrict__ w3,
                          __half* __restrict__ ox, __half* __restrict__ ow)
{
    int t = (blockIdx.x * 256 + threadIdx.x) * 4;
    int seg = t >> 22;
    const float* src;
    __half* dst;
    if (seg < 2)      { src = x + t;            dst = ox + t; }
    else if (seg == 2){ src = w0 + (t & (NW_-1)); dst = ow + t - NX_; }
    else if (seg == 3){ src = w1 + (t & (NW_-1)); dst = ow + t - NX_; }
    else if (seg == 4){ src = w2 + (t & (NW_-1)); dst = ow + t - NX_; }
    else              { src = w3 + (t & (NW_-1)); dst = ow + t - NX_; }
    float4 v = *(const float4*)src;
    ((__half2*)dst)[0] = __floats2half2_rn(v.x, v.y);
    ((__half2*)dst)[1] = __floats2half2_rn(v.z, v.w);
}

// ---------------------------------------------------------------------------
extern "C" void kernel_launch(void* const* d_in, const int* in_sizes, int n_in,
                              void* d_out, int out_size)
{
    const float* x  = (const float*)d_in[0];
    const float* fc = (const float*)d_in[1];
    const float* fs = (const float*)d_in[2];
    const float* wq = (const float*)d_in[3];
    const float* bq = (const float*)d_in[4];
    const float* wk = (const float*)d_in[5];
    const float* bk = (const float*)d_in[6];
    const float* wv = (const float*)d_in[7];
    const float* bv = (const float*)d_in[8];
    const float* wo = (const float*)d_in[9];
    const float* bo = (const float*)d_in[10];
    float* out = (float*)d_out;

    float *pMp;
    __half *pxf, *pw, *paf, *pqf, *pktf, *pvt, *pmtf;
    cudaGetSymbolAddress((void**)&pMp, g_Mp);
    cudaGetSymbolAddress((void**)&pxf, g_xf);
    cudaGetSymbolAddress((void**)&pw,  g_w);
    cudaGetSymbolAddress((void**)&paf, g_af);
    cudaGetSymbolAddress((void**)&pqf, g_qf);
    cudaGetSymbolAddress((void**)&pktf, g_ktf);
    cudaGetSymbolAddress((void**)&pvt, g_vt);
    cudaGetSymbolAddress((void**)&pmtf, g_mtf);

    cudaFuncSetAttribute(gemm_qkv,  cudaFuncAttributeMaxDynamicSharedMemorySize, GEMM1_SMEM);
    cudaFuncSetAttribute(gemm_wo,   cudaFuncAttributeMaxDynamicSharedMemorySize, GEMM1_SMEM);
    cudaFuncSetAttribute(kv_hmma,   cudaFuncAttributeMaxDynamicSharedMemorySize, GEMM1_SMEM);
    cudaFuncSetAttribute(attn_hmma, cudaFuncAttributeMaxDynamicSharedMemorySize, GEMM1_SMEM);

    dim3 blk(256);
    const size_t WSTRIDE = (size_t)NW_;

    round_all<<<(NX_ + 4 * NW_) / 1024, blk>>>(x, wq, wk, wv, wo, pxf, pw);

    gemm_qkv<<<dim3(48, 32), blk, GEMM1_SMEM>>>(pxf, pw, bq, bk, bv, fc, fs,
                                                pqf, pktf, pvt);

    kv_hmma<<<dim3(KVSPLIT, 32), blk, GEMM1_SMEM>>>(pktf, pvt, pMp);

    reduce_mt<<<(32 * HD_ * HD_ / 2) / 256, blk>>>(pMp, pmtf);

    attn_hmma<<<dim3(16, 32), blk, GEMM1_SMEM>>>(pqf, pmtf, paf);

    gemm_wo<<<dim3(16, 32), blk, GEMM1_SMEM>>>(paf, pw + 3 * WSTRIDE, bo, out);
}

// round 17
// speedup vs baseline: 1.1589x; 1.0615x over previous
#include <cuda_runtime.h>
#include <cuda_fp16.h>
#include <cstdint>

#define B_  2
#define S_  2048
#define DIM_ 2048
#define NH_ 16
#define HD_ 128
#define MROWS (B_*S_)          // 4096
#define KVSPLIT 16
#define NW_ (DIM_*DIM_)        // 4194304 = 2^22
#define NX_ (MROWS*DIM_)       // 8388608 = 2*2^22

// ---------------- scratch (device globals; no allocation) ----------------
__device__ __align__(16) float g_Mp[(size_t)KVSPLIT * B_ * NH_ * HD_ * HD_];

__device__ __align__(16) __half g_xf[(size_t)NX_];
__device__ __align__(16) __half g_w[4][(size_t)NW_];
__device__ __align__(16) __half g_af[(size_t)NX_];
__device__ __align__(16) __half g_qf[(size_t)NX_];
__device__ __align__(16) __half g_ktf[(size_t)B_ * NH_ * HD_ * S_];
__device__ __align__(16) __half g_vt [(size_t)B_ * NH_ * HD_ * S_];
__device__ __align__(16) __half g_mtf[(size_t)B_ * NH_ * HD_ * HD_];

// ======================= PTX helpers ==========================
__device__ __forceinline__ uint32_t smem_u32(const void* p) {
    uint32_t a;
    asm("{ .reg .u64 t; cvta.to.shared.u64 t, %1; cvt.u32.u64 %0, t; }"
        : "=r"(a) : "l"(p));
    return a;
}

__device__ __forceinline__ void ldsm_x4(uint32_t* r, uint32_t addr) {
    asm volatile("ldmatrix.sync.aligned.m8n8.x4.shared.b16 {%0,%1,%2,%3}, [%4];"
                 : "=r"(r[0]), "=r"(r[1]), "=r"(r[2]), "=r"(r[3]) : "r"(addr));
}

__device__ __forceinline__ void mma_f16(float* d, const uint32_t* a, const uint32_t* b) {
    asm volatile(
        "mma.sync.aligned.m16n8k16.row.col.f32.f16.f16.f32 "
        "{%0,%1,%2,%3}, {%4,%5,%6,%7}, {%8,%9}, {%0,%1,%2,%3};"
        : "+f"(d[0]), "+f"(d[1]), "+f"(d[2]), "+f"(d[3])
        : "r"(a[0]), "r"(a[1]), "r"(a[2]), "r"(a[3]), "r"(b[0]), "r"(b[1]));
}

#define CP_ASYNC16(dst, src) \
    asm volatile("cp.async.cg.shared.global [%0], [%1], 16;" :: "r"(dst), "l"(src))
#define CP_COMMIT() asm volatile("cp.async.commit_group;" ::: "memory")
#define CP_WAIT0()  asm volatile("cp.async.wait_group 0;" ::: "memory")
#define CP_WAIT1()  asm volatile("cp.async.wait_group 1;" ::: "memory")

#define SW128(bo) ((bo) ^ (((bo) >> 3) & 0x70))

#define ACC_INIT4(acc) \
    _Pragma("unroll") for (int i = 0; i < 4; i++) \
    _Pragma("unroll") for (int j = 0; j < 4; j++) \
    _Pragma("unroll") for (int q = 0; q < 4; q++) acc[i][j][q] = 0.f;

// ============ fp16 1-pass 128x128 mainloop, 3-stage, single barrier ========
#define STAGE1_BYTES 32768
#define GEMM1_SMEM   (3 * STAGE1_BYTES)

__device__ __forceinline__ void mm_tile1(
    const __half* Af, const __half* Bf,
    int lda, int ldb, int chunks, char* smem, float (&acc)[4][4][4])
{
    const uint32_t sbase = smem_u32(smem);
    const int tid  = threadIdx.x;
    const int lane = tid & 31;
    const int w    = tid >> 5;
    const int wm   = (w & 1) * 64;
    const int wn   = (w >> 1) * 32;

    auto stage_load = [&](int buf, int kbase) {
        const uint32_t sp0 = sbase + buf * STAGE1_BYTES;
#pragma unroll
        for (int m = 0; m < 2; m++) {
            const __half* gp = (m ? Bf : Af) + kbase;
            const int ld = m ? ldb : lda;
            const uint32_t sp = sp0 + m * 16384;
#pragma unroll
            for (int j = 0; j < 4; j++) {
                int id  = j * 256 + tid;
                int row = id >> 3;
                int ch  = id & 7;
                uint32_t bo = row * 128 + ch * 16;
                CP_ASYNC16(sp + SW128(bo), (const char*)(gp + (size_t)row * ld) + ch * 16);
            }
        }
    };

    stage_load(0, 0);
    CP_COMMIT();
    if (chunks > 1) { stage_load(1, 64); CP_COMMIT(); }

    const int a_row  = lane & 15;
    const int a_koff = (lane >> 4) * 16;
    const int b_row  = (lane & 7) + ((lane >> 4) << 3);
    const int b_koff = ((lane >> 3) & 1) * 16;

    int buf = 0;
    for (int c = 0; c < chunks; c++) {
        if (c + 1 < chunks) CP_WAIT1(); else CP_WAIT0();
        __syncthreads();
        if (c + 2 < chunks) {
            int nb = buf + 2; if (nb >= 3) nb -= 3;
            stage_load(nb, (c + 2) * 64);
            CP_COMMIT();
        }

        const uint32_t sA = sbase + buf * STAGE1_BYTES;
        const uint32_t sB = sA + 16384;

#pragma unroll
        for (int ks = 0; ks < 4; ks++) {
            const int kb2 = ks * 32;
            uint32_t af[4][4], bf[2][4];
#pragma unroll
            for (int mt = 0; mt < 4; mt++) {
                uint32_t bo = (wm + mt * 16 + a_row) * 128 + kb2 + a_koff;
                ldsm_x4(af[mt], sA + SW128(bo));
            }
#pragma unroll
            for (int bt = 0; bt < 2; bt++) {
                uint32_t bo = (wn + bt * 16 + b_row) * 128 + kb2 + b_koff;
                ldsm_x4(bf[bt], sB + SW128(bo));
            }
#pragma unroll
            for (int mt = 0; mt < 4; mt++) {
#pragma unroll
                for (int nt = 0; nt < 4; nt++) {
                    const uint32_t* bp = &bf[nt >> 1][(nt & 1) * 2];
                    mma_f16(acc[mt][nt], af[mt], bp);
                }
            }
        }
        if (++buf == 3) buf = 0;
    }
}

// ============ fused QKV GEMM + rope/round/transpose epilogue ===============
// grid (48, 32). Column tile == one head (HD==128).
__global__ void __launch_bounds__(256, 2)
gemm_qkv(const __half* __restrict__ xf, const __half* __restrict__ wf,
         const float* __restrict__ bq, const float* __restrict__ bk,
         const float* __restrict__ bv,
         const float* __restrict__ fc, const float* __restrict__ fs,
         __half* __restrict__ qf, __half* __restrict__ ktf,
         __half* __restrict__ vt)
{
    extern __shared__ char smem[];
    const int bx = blockIdx.x, by = blockIdx.y;
    const int wsel = bx >> 4;
    const int col0 = (bx & 15) * 128;
    const int row0 = by * 128;

    float acc[4][4][4];
    ACC_INIT4(acc)
    mm_tile1(xf + (size_t)row0 * DIM_, wf + (size_t)bx * 128 * DIM_,
             DIM_, DIM_, DIM_ / 64, smem, acc);

    // single-barrier mainloop has no trailing sync; the transpose buffer below
    // overlaps stage memory, so order all lagging consumers before reuse.
    __syncthreads();

    const int tid  = threadIdx.x;
    const int lane = tid & 31, w = tid >> 5;
    const int wm = (w & 1) * 64, wn = (w >> 1) * 32;
    const int l4 = lane >> 2, l2 = (lane & 3) * 2;

    const int s0 = (by & 15) * 128;   // s offset within batch
    const int b  = by >> 4;
    const int h  = bx & 15;

    if (wsel == 0) {
        // ---- Q: bias + rope + round, row-major ----
#pragma unroll
        for (int mt = 0; mt < 4; mt++) {
#pragma unroll
            for (int nt = 0; nt < 4; nt++) {
                const int cl = wn + nt * 8 + l2;        // even, within-head dim
                const int i  = cl >> 1;
                const float b0 = __ldg(bq + col0 + cl);
                const float b1 = __ldg(bq + col0 + cl + 1);
#pragma unroll
                for (int rr = 0; rr < 2; rr++) {
                    const int sl = wm + mt * 16 + l4 + rr * 8;
                    const int sg = s0 + sl;
                    const float c  = __ldg(fc + sg * 64 + i);
                    const float sn = __ldg(fs + sg * 64 + i);
                    const float v0 = acc[mt][nt][rr * 2 + 0] + b0;
                    const float v1 = acc[mt][nt][rr * 2 + 1] + b1;
                    const float o0 = v0 * c - v1 * sn;
                    const float o1 = v0 * sn + v1 * c;
                    const size_t off = (size_t)(row0 + sl) * DIM_ + col0 + cl;
                    *(__half2*)(qf + off) = __floats2half2_rn(o0, o1);
                }
            }
        }
    } else {
        // ---- K / V: round into transposed smem buffer [128 d][136] ----
        __half* sh = (__half*)smem;
        const float* bias = (wsel == 1) ? bk : bv;
#pragma unroll
        for (int mt = 0; mt < 4; mt++) {
#pragma unroll
            for (int nt = 0; nt < 4; nt++) {
                const int cl = wn + nt * 8 + l2;
                const float b0 = __ldg(bias + col0 + cl);
                const float b1 = __ldg(bias + col0 + cl + 1);
#pragma unroll
                for (int rr = 0; rr < 2; rr++) {
                    const int sl = wm + mt * 16 + l4 + rr * 8;
                    float v0 = acc[mt][nt][rr * 2 + 0] + b0;
                    float v1 = acc[mt][nt][rr * 2 + 1] + b1;
                    if (wsel == 1) {
                        const int i  = cl >> 1;
                        const int sg = s0 + sl;
                        const float c  = __ldg(fc + sg * 64 + i);
                        const float sn = __ldg(fs + sg * 64 + i);
                        const float o0 = v0 * c - v1 * sn;
                        const float o1 = v0 * sn + v1 * c;
                        v0 = o0; v1 = o1;
                    }
                    sh[cl * 136 + sl]       = __float2half(v0);
                    sh[(cl + 1) * 136 + sl] = __float2half(v1);
                }
            }
        }
        __syncthreads();
        // coalesced store: warp w writes rows 16w..16w+15; per STG two rows,
        // 16 lanes x 16B contiguous per row (2 x 256B segments).
        const size_t tb = ((size_t)(b * NH_ + h)) * HD_ * S_ + s0;
        const int lrow = lane >> 4;           // 0/1
        const int loff = (lane & 15) * 8;     // halves
        __half* dst = (wsel == 1) ? ktf : vt;
#pragma unroll
        for (int j = 0; j < 8; j++) {
            const int d = w * 16 + j * 2 + lrow;
            const size_t go = tb + (size_t)d * S_ + loff;
            *(uint4*)(dst + go) = *(const uint4*)&sh[d * 136 + loff];
        }
    }
}

// ============ WO GEMM: grid (16, 32) =======================================
__global__ void __launch_bounds__(256, 2)
gemm_wo(const __half* __restrict__ Af, const __half* __restrict__ Bf,
        const float* __restrict__ bias, float* __restrict__ C)
{
    extern __shared__ char smem[];
    const int row0 = blockIdx.y * 128;
    const int col0 = blockIdx.x * 128;

    float acc[4][4][4];
    ACC_INIT4(acc)
    mm_tile1(Af + (size_t)row0 * DIM_, Bf + (size_t)col0 * DIM_,
             DIM_, DIM_, DIM_ / 64, smem, acc);

    const int lane = threadIdx.x & 31, w = threadIdx.x >> 5;
    const int wm = (w & 1) * 64, wn = (w >> 1) * 32;
    const int l4 = lane >> 2, l2 = (lane & 3) * 2;
#pragma unroll
    for (int mt = 0; mt < 4; mt++) {
#pragma unroll
        for (int nt = 0; nt < 4; nt++) {
            int grow = row0 + wm + mt * 16 + l4;
            int gcol = col0 + wn + nt * 8 + l2;
            float b0 = __ldg(bias + gcol);
            float b1 = __ldg(bias + gcol + 1);
            float* cp0 = C + (size_t)grow * DIM_ + gcol;
            float* cp1 = cp0 + 8 * (size_t)DIM_;
            *(float2*)cp0 = make_float2(acc[mt][nt][0] + b0, acc[mt][nt][1] + b1);
            *(float2*)cp1 = make_float2(acc[mt][nt][2] + b0, acc[mt][nt][3] + b1);
        }
    }
}

// ============ VtK GEMM (fp16 1-pass): grid (KVSPLIT, 32) ===================
// Operands swapped vs kv of old rounds: C[dout][d2q] = sum_s V[s,dout]*K[s,d2q]
// -> Mp already in the mtf layout; reduce_mt becomes fully linear/coalesced.
__global__ void __launch_bounds__(256, 2)
kv_hmma(const __half* __restrict__ ktf, const __half* __restrict__ vt,
        float* __restrict__ Mp)
{
    extern __shared__ char smem[];
    const int ksp = blockIdx.x;
    const int bh  = blockIdx.y;
    const size_t base = (size_t)bh * HD_ * S_ + ksp * (S_ / KVSPLIT);

    float acc[4][4][4];
    ACC_INIT4(acc)
    mm_tile1(vt + base, ktf + base, S_, S_, (S_ / KVSPLIT) / 64, smem, acc);

    float* C = Mp + ((size_t)ksp * 32 + bh) * (HD_ * HD_);
    const int lane = threadIdx.x & 31, w = threadIdx.x >> 5;
    const int wm = (w & 1) * 64, wn = (w >> 1) * 32;
    const int l4 = lane >> 2, l2 = (lane & 3) * 2;
#pragma unroll
    for (int mt = 0; mt < 4; mt++) {
#pragma unroll
        for (int nt = 0; nt < 4; nt++) {
            int grow = wm + mt * 16 + l4;
            int gcol = wn + nt * 8 + l2;
            float* cp0 = C + (size_t)grow * HD_ + gcol;
            float* cp1 = cp0 + 8 * HD_;
            *(float2*)cp0 = make_float2(acc[mt][nt][0], acc[mt][nt][1]);
            *(float2*)cp1 = make_float2(acc[mt][nt][2], acc[mt][nt][3]);
        }
    }
}

// ============ attn GEMM (fp16 1-pass): grid (16,32) ========================
__global__ void __launch_bounds__(256, 2)
attn_hmma(const __half* __restrict__ qf, const __half* __restrict__ mtf,
          __half* __restrict__ af)
{
    extern __shared__ char smem[];
    const int st = blockIdx.x;
    const int bh = blockIdx.y;
    const int b = bh >> 4, h = bh & 15;
    const size_t abase = ((size_t)(b * S_ + st * 128)) * DIM_ + h * HD_;
    const size_t mbase = (size_t)bh * HD_ * HD_;

    float acc[4][4][4];
    ACC_INIT4(acc)
    mm_tile1(qf + abase, mtf + mbase, DIM_, HD_, HD_ / 64, smem, acc);

    const int lane = threadIdx.x & 31, w = threadIdx.x >> 5;
    const int wm = (w & 1) * 64, wn = (w >> 1) * 32;
    const int l4 = lane >> 2, l2 = (lane & 3) * 2;
#pragma unroll
    for (int mt = 0; mt < 4; mt++) {
#pragma unroll
        for (int nt = 0; nt < 4; nt++) {
            size_t off0 = abase + (size_t)(wm + mt * 16 + l4) * DIM_ + wn + nt * 8 + l2;
            size_t off1 = off0 + 8 * (size_t)DIM_;
            *(__half2*)(af + off0) = __floats2half2_rn(acc[mt][nt][0], acc[mt][nt][1]);
            *(__half2*)(af + off1) = __floats2half2_rn(acc[mt][nt][2], acc[mt][nt][3]);
        }
    }
}

// ============ reduce Mp over splits, scale, round (fully coalesced) ========
__global__ void reduce_mt(const float* __restrict__ Mp, __half* __restrict__ mt)
{
    int o = (blockIdx.x * 256 + threadIdx.x) * 2;   // linear over 32*16384
    const size_t stride = (size_t)32 * HD_ * HD_;
    float s0 = 0.f, s1 = 0.f;
#pragma unroll
    for (int p = 0; p < KVSPLIT; p++) {
        float2 v = *(const float2*)(Mp + p * stride + o);
        s0 += v.x;
        s1 += v.y;
    }
    s0 *= 0.08838834764831845f;
    s1 *= 0.08838834764831845f;
    *(__half2*)(mt + o) = __floats2half2_rn(s0, s1);
}

// ---------------- fused x + 4-weight fp32 -> fp16 round --------------------
// segments of 2^22 elems: [0,1]=x, [2..5]=wq,wk,wv,wo
__global__ void round_all(const float* __restrict__ x,
                          const float* __restrict__ w0, const float* __restrict__ w1,
                          const float* __restrict__ w2, const float* __restrict__ w3,
                          __half* __restrict__ ox, __half* __restrict__ ow)
{
    int t = (blockIdx.x * 256 + threadIdx.x) * 4;
    int seg = t >> 22;
    const float* src;
    __half* dst;
    if (seg < 2)      { src = x + t;              dst = ox + t; }
    else if (seg == 2){ src = w0 + (t & (NW_-1)); dst = ow + t - NX_; }
    else if (seg == 3){ src = w1 + (t & (NW_-1)); dst = ow + t - NX_; }
    else if (seg == 4){ src = w2 + (t & (NW_-1)); dst = ow + t - NX_; }
    else              { src = w3 + (t & (NW_-1)); dst = ow + t - NX_; }
    float4 v = *(const float4*)src;
    ((__half2*)dst)[0] = __floats2half2_rn(v.x, v.y);
    ((__half2*)dst)[1] = __floats2half2_rn(v.z, v.w);
}

// ---------------------------------------------------------------------------
extern "C" void kernel_launch(void* const* d_in, const int* in_sizes, int n_in,
                              void* d_out, int out_size)
{
    const float* x  = (const float*)d_in[0];
    const float* fc = (const float*)d_in[1];
    const float* fs = (const float*)d_in[2];
    const float* wq = (const float*)d_in[3];
    const float* bq = (const float*)d_in[4];
    const float* wk = (const float*)d_in[5];
    const float* bk = (const float*)d_in[6];
    const float* wv = (const float*)d_in[7];
    const float* bv = (const float*)d_in[8];
    const float* wo = (const float*)d_in[9];
    const float* bo = (const float*)d_in[10];
    float* out = (float*)d_out;

    float *pMp;
    __half *pxf, *pw, *paf, *pqf, *pktf, *pvt, *pmtf;
    cudaGetSymbolAddress((void**)&pMp, g_Mp);
    cudaGetSymbolAddress((void**)&pxf, g_xf);
    cudaGetSymbolAddress((void**)&pw,  g_w);
    cudaGetSymbolAddress((void**)&paf, g_af);
    cudaGetSymbolAddress((void**)&pqf, g_qf);
    cudaGetSymbolAddress((void**)&pktf, g_ktf);
    cudaGetSymbolAddress((void**)&pvt, g_vt);
    cudaGetSymbolAddress((void**)&pmtf, g_mtf);

    cudaFuncSetAttribute(gemm_qkv,  cudaFuncAttributeMaxDynamicSharedMemorySize, GEMM1_SMEM);
    cudaFuncSetAttribute(gemm_wo,   cudaFuncAttributeMaxDynamicSharedMemorySize, GEMM1_SMEM);
    cudaFuncSetAttribute(kv_hmma,   cudaFuncAttributeMaxDynamicSharedMemorySize, GEMM1_SMEM);
    cudaFuncSetAttribute(attn_hmma, cudaFuncAttributeMaxDynamicSharedMemorySize, GEMM1_SMEM);

    dim3 blk(256);
    const size_t WSTRIDE = (size_t)NW_;

    round_all<<<(NX_ + 4 * NW_) / 1024, blk>>>(x, wq, wk, wv, wo, pxf, pw);

    gemm_qkv<<<dim3(48, 32), blk, GEMM1_SMEM>>>(pxf, pw, bq, bk, bv, fc, fs,
                                                pqf, pktf, pvt);

    kv_hmma<<<dim3(KVSPLIT, 32), blk, GEMM1_SMEM>>>(pktf, pvt, pMp);

    reduce_mt<<<(32 * HD_ * HD_ / 2) / 256, blk>>>(pMp, pmtf);

    attn_hmma<<<dim3(16, 32), blk, GEMM1_SMEM>>>(pqf, pmtf, paf);

    gemm_wo<<<dim3(16, 32), blk, GEMM1_SMEM>>>(paf, pw + 3 * WSTRIDE, bo, out);
}